// round 13
// baseline (speedup 1.0000x reference)
#include <cuda_runtime.h>
#include <cuda_fp16.h>
#include <stdint.h>
#include <stddef.h>

#define GROUP 64
#define MAXT 4096
#define MAXN 4096
#define KMAX 4096

// Scratch (device globals: allocation-free rule)
__device__ uint8_t g_Aq[(size_t)MAXT * KMAX];    // e4m3 quantized activations
__device__ uint8_t g_Bq[(size_t)MAXN * KMAX];    // e4m3 weights
__device__ float   g_Asc[(size_t)MAXT * 64];     // activation scales [T][K/64]
__device__ __half  g_Alr[(size_t)MAXT * 64];     // lr augmented A cols (fp16)
__device__ __half  g_Blr[(size_t)MAXN * 64];     // lr augmented B cols (fp16)
__device__ float   g_LRp[16][MAXT][32];          // lowrank split-K partials
__device__ int     g_wfmt;                       // 0=int8, 1=int32, 2=float32

// ---------------------------------------------------------------------------
// helpers
// ---------------------------------------------------------------------------
__device__ __forceinline__ uint32_t smem_u32(const void* p) {
    uint32_t a;
    asm("{ .reg .u64 t; cvta.to.shared.u64 t, %1; cvt.u32.u64 %0, t; }" : "=r"(a) : "l"(p));
    return a;
}
#define SWZ(o) ((o) ^ ((((uint32_t)(o)) >> 3) & 0x70))

__device__ __forceinline__ void cp16(uint32_t s, const void* g) {
    asm volatile("cp.async.cg.shared.global [%0], [%1], 16;" :: "r"(s), "l"(g));
}
__device__ __forceinline__ void cp8(uint32_t s, const void* g) {
    asm volatile("cp.async.ca.shared.global [%0], [%1], 8;" :: "r"(s), "l"(g));
}
__device__ __forceinline__ void ldmx4(uint32_t& r0, uint32_t& r1, uint32_t& r2, uint32_t& r3,
                                      uint32_t addr) {
    asm volatile("ldmatrix.sync.aligned.m8n8.x4.shared.b16 {%0,%1,%2,%3}, [%4];"
                 : "=r"(r0), "=r"(r1), "=r"(r2), "=r"(r3) : "r"(addr));
}
__device__ __forceinline__ void mma16816(float& c0, float& c1, float& c2, float& c3,
                                         uint32_t a0, uint32_t a1, uint32_t a2, uint32_t a3,
                                         uint32_t b0, uint32_t b1) {
    asm volatile("mma.sync.aligned.m16n8k16.row.col.f32.f16.f16.f32 "
                 "{%0,%1,%2,%3}, {%4,%5,%6,%7}, {%8,%9}, {%0,%1,%2,%3};"
                 : "+f"(c0), "+f"(c1), "+f"(c2), "+f"(c3)
                 : "r"(a0), "r"(a1), "r"(a2), "r"(a3), "r"(b0), "r"(b1));
}
__device__ __forceinline__ void mmafp8(float& c0, float& c1, float& c2, float& c3,
                                       uint32_t a0, uint32_t a1, uint32_t a2, uint32_t a3,
                                       uint32_t b0, uint32_t b1) {
    asm volatile("mma.sync.aligned.m16n8k32.row.col.f32.e4m3.e4m3.f32 "
                 "{%0,%1,%2,%3}, {%4,%5,%6,%7}, {%8,%9}, {%0,%1,%2,%3};"
                 : "+f"(c0), "+f"(c1), "+f"(c2), "+f"(c3)
                 : "r"(a0), "r"(a1), "r"(a2), "r"(a3), "r"(b0), "r"(b1));
}
// pack 4 floats (integral, in [-8,7]) into 4 e4m3 bytes (exact for these values)
__device__ __forceinline__ uint32_t pack_e4m3_4(float f0, float f1, float f2, float f3) {
    uint16_t lo, hi;
    asm("cvt.rn.satfinite.e4m3x2.f32 %0, %1, %2;" : "=h"(lo) : "f"(f1), "f"(f0));
    asm("cvt.rn.satfinite.e4m3x2.f32 %0, %1, %2;" : "=h"(hi) : "f"(f3), "f"(f2));
    return (uint32_t)lo | ((uint32_t)hi << 16);
}

// ---------------------------------------------------------------------------
// Kernel 0: detect storage format of q_w (harness may widen int8)
// ---------------------------------------------------------------------------
__global__ void detect_wfmt_kernel(const void* qw, int total) {
    __shared__ int ok_i32, ok_f32;
    if (threadIdx.x == 0) { ok_i32 = 1; ok_f32 = 1; }
    __syncthreads();
    const int*   wi = (const int*)qw;
    const float* wf = (const float*)qw;
    int n = total < 1024 ? total : 1024;
    int bad_i = 0, bad_f = 0;
    for (int i = threadIdx.x; i < n; i += blockDim.x) {
        int v = wi[i];
        if (v < -8 || v > 7) bad_i = 1;
        float f = wf[i];
        if (!(f == rintf(f) && fabsf(f) <= 8.f)) bad_f = 1;
    }
    if (bad_i) atomicAnd(&ok_i32, 0);
    if (bad_f) atomicAnd(&ok_f32, 0);
    __syncthreads();
    if (threadIdx.x == 0)
        g_wfmt = ok_i32 ? 1 : (ok_f32 ? 2 : 0);
}

// ---------------------------------------------------------------------------
// Fused prep kernel: blockIdx ranges dispatch to
//   [0, LRB)            lowrank split-K partials (long pole first)
//   [LRB, LRB+QB)       activation quant -> e4m3 + scales
//   [LRB+QB, +PB)       weight pack -> e4m3
//   [.., +AB)           B augmented lr columns
// ---------------------------------------------------------------------------
__global__ void __launch_bounds__(256) prep_kernel(
    const float* __restrict__ x, const float* __restrict__ smooth,
    const float* __restrict__ pd, const float* __restrict__ pu,
    const void* __restrict__ qw,
    int T, int K, int R, int N,
    int LRB, int QB, int PB, int AB)
{
    __shared__ float xs[128 * 33];
    __shared__ float pdt[32 * 33];
    int tid = threadIdx.x;
    int b = blockIdx.x;

    if (b < LRB) {
        // ---- lowrank split-K partials: 16 slices x (T/128) tiles ----
        int kb = b & 15, tb = b >> 4;
        int t0 = tb * 128;
        int kl = K >> 4;                 // 256
        int k0 = kb * kl;
        int tg = tid >> 3, rb = (tid & 7) * 4;

        float acc[4][4];
#pragma unroll
        for (int i = 0; i < 4; ++i)
#pragma unroll
            for (int j = 0; j < 4; ++j) acc[i][j] = 0.f;

        for (int kt = 0; kt < kl; kt += 32) {
#pragma unroll
            for (int i = 0; i < 4; ++i) {
                int idx4 = tid + i * 256;            // 1024 float4 = 128 x 8
                int row = idx4 >> 3, c4 = idx4 & 7;
                float4 v = *reinterpret_cast<const float4*>(
                    x + (size_t)(t0 + row) * K + k0 + kt + c4 * 4);
                float4 s = *reinterpret_cast<const float4*>(smooth + k0 + kt + c4 * 4);
                v.x *= s.x; v.y *= s.y; v.z *= s.z; v.w *= s.w;
                float* d = &xs[row * 33 + c4 * 4];
                d[0] = v.x; d[1] = v.y; d[2] = v.z; d[3] = v.w;
            }
#pragma unroll
            for (int i = 0; i < 4; ++i) {
                int e = tid + i * 256;               // 1024 = 32 kk x 32 r
                int kk = e >> 5, r = e & 31;
                pdt[kk * 33 + r] = (r < R) ? pd[(size_t)(k0 + kt + kk) * R + r] : 0.f;
            }
            __syncthreads();
#pragma unroll 8
            for (int kk = 0; kk < 32; ++kk) {
                float p0 = pdt[kk * 33 + rb + 0];
                float p1 = pdt[kk * 33 + rb + 1];
                float p2 = pdt[kk * 33 + rb + 2];
                float p3 = pdt[kk * 33 + rb + 3];
#pragma unroll
                for (int i = 0; i < 4; ++i) {
                    float xv = xs[(tg * 4 + i) * 33 + kk];
                    acc[i][0] = fmaf(xv, p0, acc[i][0]);
                    acc[i][1] = fmaf(xv, p1, acc[i][1]);
                    acc[i][2] = fmaf(xv, p2, acc[i][2]);
                    acc[i][3] = fmaf(xv, p3, acc[i][3]);
                }
            }
            __syncthreads();
        }
#pragma unroll
        for (int i = 0; i < 4; ++i) {
            int t = t0 + tg * 4 + i;
#pragma unroll
            for (int j = 0; j < 4; ++j)
                g_LRp[kb][t][rb + j] = acc[i][j];
        }
        return;
    }
    b -= LRB;

    if (b < QB) {
        // ---- activation quantization -> e4m3 + scales ----
        int g = b * 256 + tid;
        int gpr = K / GROUP;
        if (g >= T * gpr) return;
        int t = g / gpr, gc = g % gpr;
        const float4* xg = reinterpret_cast<const float4*>(x + (size_t)t * K + (size_t)gc * GROUP);
        const float4* sm = reinterpret_cast<const float4*>(smooth + (size_t)gc * GROUP);

        float amax = 0.f;
#pragma unroll
        for (int i = 0; i < 16; ++i) {
            float4 v = xg[i]; float4 s = sm[i];
            v.x *= s.x; v.y *= s.y; v.z *= s.z; v.w *= s.w;
            amax = fmaxf(amax, fmaxf(fmaxf(fabsf(v.x), fabsf(v.y)), fmaxf(fabsf(v.z), fabsf(v.w))));
        }
        float scale = fmaxf(amax * (1.0f / 7.0f), 1e-8f);
        float inv = 1.0f / scale;
        g_Asc[(size_t)t * gpr + gc] = scale;

        uint32_t* dst = reinterpret_cast<uint32_t*>(g_Aq + (size_t)t * K + (size_t)gc * GROUP);
#pragma unroll
        for (int i = 0; i < 16; ++i) {
            float4 v = xg[i]; float4 s = sm[i];
            v.x *= s.x; v.y *= s.y; v.z *= s.z; v.w *= s.w;
            float q0 = fminf(fmaxf(rintf(v.x * inv), -8.f), 7.f);
            float q1 = fminf(fmaxf(rintf(v.y * inv), -8.f), 7.f);
            float q2 = fminf(fmaxf(rintf(v.z * inv), -8.f), 7.f);
            float q3 = fminf(fmaxf(rintf(v.w * inv), -8.f), 7.f);
            dst[i] = pack_e4m3_4(q0, q1, q2, q3);
        }
        return;
    }
    b -= QB;

    if (b < PB) {
        // ---- weight pack -> e4m3 (format-adaptive) ----
        int idx = b * 256 + tid;     // one per 16 weights
        int per_row = K / 16;
        if (idx >= N * per_row) return;
        size_t base = (size_t)idx * 16;

        uint32_t out[4];
        int fmt = g_wfmt;
        if (fmt == 1) {
            const int4* p = reinterpret_cast<const int4*>((const int*)qw + base);
#pragma unroll
            for (int i = 0; i < 4; ++i) {
                int4 v = p[i];
                out[i] = pack_e4m3_4((float)v.x, (float)v.y, (float)v.z, (float)v.w);
            }
        } else if (fmt == 2) {
            const float4* p = reinterpret_cast<const float4*>((const float*)qw + base);
#pragma unroll
            for (int i = 0; i < 4; ++i) {
                float4 v = p[i];
                out[i] = pack_e4m3_4(v.x, v.y, v.z, v.w);
            }
        } else {
            const int8_t* p = (const int8_t*)qw + base;
#pragma unroll
            for (int i = 0; i < 4; ++i)
                out[i] = pack_e4m3_4((float)p[i * 4 + 0], (float)p[i * 4 + 1],
                                     (float)p[i * 4 + 2], (float)p[i * 4 + 3]);
        }
        int4 w;
        w.x = out[0]; w.y = out[1]; w.z = out[2]; w.w = out[3];
        *reinterpret_cast<int4*>(g_Bq + base) = w;
        return;
    }
    b -= PB;

    {
        // ---- B augmented lr columns ----
        int n = b * 256 + tid;
        if (n >= N) return;
        __half* dst = g_Blr + (size_t)n * 64;
#pragma unroll 8
        for (int r = 0; r < 64; ++r)
            dst[r] = __float2half((r < R) ? pu[(size_t)r * N + n] : 0.f);
    }
}

// ---------------------------------------------------------------------------
// Reduce lowrank partials -> g_Alr (fp16), zero cols 32..63
// ---------------------------------------------------------------------------
__global__ void lowrank_reduce_kernel(int T) {
    int i = blockIdx.x * 256 + threadIdx.x;
    if (i >= T * 64) return;
    int t = i >> 6, r = i & 63;
    float s = 0.f;
    if (r < 32) {
#pragma unroll
        for (int k = 0; k < 16; ++k) s += g_LRp[k][t][r];
    }
    g_Alr[(size_t)t * 64 + r] = __float2half(s);
}

// ---------------------------------------------------------------------------
// Main GEMM. Inner-loop semantics identical to the 566us R8 version, but
// warp tile 16x32 (accf 16 regs) and TILE 64x64 with 256 threads so THREE
// CTAs fit per SM (launch_bounds(256,3) -> regs<=85) = 24 warps/SM.
// 32 fp8 chunks (k=128, e4m3 MMA + per-group rescale) + 1 fp16 lr chunk,
// 3-stage cp.async pipeline.
// ---------------------------------------------------------------------------
#define THREADS 256
#define TILE_M 64
#define TILE_N 64
#define NCH 32                 // fp8 chunks (k=4096); chunk NCH = fp16 lr
#define OFF_B   8192           // A tile 64x128B = 8K
#define OFF_ASC 16384          // B tile 64x128B = 8K
#define OFF_WSC 16896          // asc 64 rows x 8B = 512
#define BUFSZ   17408          // + wsc 64 rows x 8B = 512
#define STAGES 3
#define GEMM_SMEM (STAGES * BUFSZ)   // 52224

__device__ __forceinline__ void load_chunk(uint32_t sb, int buf, int c,
                                           int m0, int n0, const float* ws, int tid) {
    uint32_t base = sb + buf * BUFSZ;
    const char* Asrc;
    const char* Bsrc;
    int stride;
    if (c < NCH) {
        Asrc = reinterpret_cast<const char*>(g_Aq) + (size_t)m0 * 4096 + c * 128;
        Bsrc = reinterpret_cast<const char*>(g_Bq) + (size_t)n0 * 4096 + c * 128;
        stride = 4096;
    } else {
        Asrc = reinterpret_cast<const char*>(g_Alr) + (size_t)m0 * 128;
        Bsrc = reinterpret_cast<const char*>(g_Blr) + (size_t)n0 * 128;
        stride = 128;
    }
    // A and B: 64 rows x 8 x 16B = 512 pieces each
#pragma unroll
    for (int i = 0; i < 2; ++i) {
        int idx = tid + i * 256;
        int row = idx >> 3, pc = idx & 7;
        uint32_t so = SWZ(row * 128 + pc * 16);
        cp16(base + so, Asrc + (size_t)row * stride + pc * 16);
        cp16(base + OFF_B + so, Bsrc + (size_t)row * stride + pc * 16);
    }
    if (c < NCH) {
        if (tid < 64)
            cp8(base + OFF_ASC + tid * 8, g_Asc + ((size_t)(m0 + tid) * 64 + 2 * c));
        else if (tid < 128)
            cp8(base + OFF_WSC + (tid - 64) * 8, ws + ((size_t)(n0 + tid - 64) * 64 + 2 * c));
    }
}

__global__ void __launch_bounds__(THREADS, 3) gemm_kernel(
    const float* __restrict__ ws, const float* __restrict__ bias,
    float* __restrict__ out, int T, int Nout)
{
    extern __shared__ char smem[];
    uint32_t sb = smem_u32(smem);
    int tid = threadIdx.x, wid = tid >> 5, lid = tid & 31;
    int wm = wid >> 1;               // 0..3  (16 rows each)
    int wn = wid & 1;                // 0..1  (32 cols each)
    int m0 = blockIdx.y * TILE_M;
    int n0 = blockIdx.x * TILE_N;

    // ldmatrix lane geometry (bytes within 128B rows, SW128)
    int r8 = lid & 7, sel = lid >> 3;
    int aRow, aXor;
    {
        int row = wm * 16 + (sel & 1) * 8 + r8;
        aRow = row * 128;
        aXor = (row & 7) << 4;
    }
    int aByte = (sel >> 1) * 16;
    int bRow[2], bXor[2];
#pragma unroll
    for (int pb = 0; pb < 2; ++pb) {
        int row = wn * 32 + pb * 16 + (sel >> 1) * 8 + r8;
        bRow[pb] = row * 128;
        bXor[pb] = (row & 7) << 4;
    }
    int bByte = (sel & 1) * 16;

    // scale lookup indices
    int sr0 = wm * 16 + (lid >> 2);          // +8 for second row
    int sc0 = wn * 32 + (lid & 3) * 2;       // + nt*8 ; +1 second col

    float accf[4][4];
#pragma unroll
    for (int nt = 0; nt < 4; ++nt)
#pragma unroll
        for (int i = 0; i < 4; ++i) accf[nt][i] = 0.f;

    load_chunk(sb, 0, 0, m0, n0, ws, tid);
    asm volatile("cp.async.commit_group;" ::: "memory");
    load_chunk(sb, 1, 1, m0, n0, ws, tid);
    asm volatile("cp.async.commit_group;" ::: "memory");

    for (int c = 0; c <= NCH; ++c) {
        if (c < NCH) { asm volatile("cp.async.wait_group 1;" ::: "memory"); }
        else         { asm volatile("cp.async.wait_group 0;" ::: "memory"); }
        __syncthreads();
        if (c + 2 <= NCH) {
            load_chunk(sb, (c + 2) % STAGES, c + 2, m0, n0, ws, tid);
            asm volatile("cp.async.commit_group;" ::: "memory");
        }
        int buf = c % STAGES;
        uint32_t ab = sb + buf * BUFSZ;
        uint32_t bb = ab + OFF_B;

        if (c < NCH) {
            const float* asc_s = reinterpret_cast<const float*>(smem + buf * BUFSZ + OFF_ASC);
            const float* wsc_s = reinterpret_cast<const float*>(smem + buf * BUFSZ + OFF_WSC);
#pragma unroll
            for (int grp = 0; grp < 2; ++grp) {
                float dg[4][4];
#pragma unroll
                for (int nt = 0; nt < 4; ++nt)
#pragma unroll
                    for (int i = 0; i < 4; ++i) dg[nt][i] = 0.f;

#pragma unroll
                for (int ks2 = 0; ks2 < 2; ++ks2) {
                    int koff = grp * 64 + ks2 * 32;
                    uint32_t a0, a1, a2, a3;
                    ldmx4(a0, a1, a2, a3, ab + aRow + ((koff + aByte) ^ aXor));
                    uint32_t b[4][2];
#pragma unroll
                    for (int pb = 0; pb < 2; ++pb) {
                        uint32_t r0, r1, r2, r3;
                        ldmx4(r0, r1, r2, r3,
                              bb + bRow[pb] + ((koff + bByte) ^ bXor[pb]));
                        b[pb * 2 + 0][0] = r0; b[pb * 2 + 0][1] = r1;
                        b[pb * 2 + 1][0] = r2; b[pb * 2 + 1][1] = r3;
                    }
#pragma unroll
                    for (int nt = 0; nt < 4; ++nt)
                        mmafp8(dg[nt][0], dg[nt][1], dg[nt][2], dg[nt][3],
                               a0, a1, a2, a3, b[nt][0], b[nt][1]);
                }
                // per-group rescale into f32 accumulators (group sums are exact ints)
                float s0 = asc_s[sr0 * 2 + grp];
                float s1 = asc_s[(sr0 + 8) * 2 + grp];
#pragma unroll
                for (int nt = 0; nt < 4; ++nt) {
                    float w0 = wsc_s[(sc0 + nt * 8) * 2 + grp];
                    float w1 = wsc_s[(sc0 + nt * 8 + 1) * 2 + grp];
                    accf[nt][0] = fmaf(dg[nt][0], s0 * w0, accf[nt][0]);
                    accf[nt][1] = fmaf(dg[nt][1], s0 * w1, accf[nt][1]);
                    accf[nt][2] = fmaf(dg[nt][2], s1 * w0, accf[nt][2]);
                    accf[nt][3] = fmaf(dg[nt][3], s1 * w1, accf[nt][3]);
                }
            }
        } else {
            // fp16 low-rank chunk (64 halves = 128B rows, same geometry)
#pragma unroll
            for (int ks = 0; ks < 4; ++ks) {
                uint32_t a0, a1, a2, a3;
                ldmx4(a0, a1, a2, a3, ab + aRow + ((ks * 32 + aByte) ^ aXor));
                uint32_t b[4][2];
#pragma unroll
                for (int pb = 0; pb < 2; ++pb) {
                    uint32_t r0, r1, r2, r3;
                    ldmx4(r0, r1, r2, r3,
                          bb + bRow[pb] + ((ks * 32 + bByte) ^ bXor[pb]));
                    b[pb * 2 + 0][0] = r0; b[pb * 2 + 0][1] = r1;
                    b[pb * 2 + 1][0] = r2; b[pb * 2 + 1][1] = r3;
                }
#pragma unroll
                for (int nt = 0; nt < 4; ++nt)
                    mma16816(accf[nt][0], accf[nt][1], accf[nt][2], accf[nt][3],
                             a0, a1, a2, a3, b[nt][0], b[nt][1]);
            }
        }
    }

    // epilogue: direct fragment stores + bias
    int g = lid >> 2, tg2 = lid & 3;
#pragma unroll
    for (int nt = 0; nt < 4; ++nt) {
        int col = n0 + wn * 32 + nt * 8 + tg2 * 2;
        float2 bv = *reinterpret_cast<const float2*>(bias + col);
        int row0 = m0 + wm * 16 + g;
        float2 v0; v0.x = accf[nt][0] + bv.x; v0.y = accf[nt][1] + bv.y;
        *reinterpret_cast<float2*>(out + (size_t)row0 * Nout + col) = v0;
        float2 v1; v1.x = accf[nt][2] + bv.x; v1.y = accf[nt][3] + bv.y;
        *reinterpret_cast<float2*>(out + (size_t)(row0 + 8) * Nout + col) = v1;
    }
}

// ---------------------------------------------------------------------------
// Host launcher
// ---------------------------------------------------------------------------
extern "C" void kernel_launch(void* const* d_in, const int* in_sizes, int n_in,
                              void* d_out, int out_size) {
    const float*  x      = (const float*)d_in[0];
    const void*   qw     = (const void*)d_in[1];
    const float*  ws     = (const float*)d_in[2];
    const float*  pd     = (const float*)d_in[3];
    const float*  pu     = (const float*)d_in[4];
    const float*  smooth = (const float*)d_in[5];
    const float*  bias   = (const float*)d_in[6];
    float* out = (float*)d_out;

    int K    = in_sizes[5];           // smooth
    int Nout = in_sizes[6];           // bias
    int T    = in_sizes[0] / K;       // x
    int R    = in_sizes[3] / K;       // proj_down

    detect_wfmt_kernel<<<1, 256>>>(qw, in_sizes[1]);

    int LRB = (T / 128) * 16;                       // 512
    int QB  = (T * (K / GROUP) + 255) / 256;        // 1024
    int PB  = (Nout * (K / 16) + 255) / 256;        // 4096
    int AB  = (Nout + 255) / 256;                   // 16
    prep_kernel<<<LRB + QB + PB + AB, 256>>>(x, smooth, pd, pu, qw,
                                             T, K, R, Nout, LRB, QB, PB, AB);
    lowrank_reduce_kernel<<<(T * 64 + 255) / 256, 256>>>(T);

    cudaFuncSetAttribute(gemm_kernel, cudaFuncAttributeMaxDynamicSharedMemorySize, GEMM_SMEM);
    dim3 grid(Nout / TILE_N, T / TILE_M);
    gemm_kernel<<<grid, THREADS, GEMM_SMEM>>>(ws, bias, out, T, Nout);
}

// round 14
// speedup vs baseline: 1.0839x; 1.0839x over previous
#include <cuda_runtime.h>
#include <cuda_fp16.h>
#include <stdint.h>
#include <stddef.h>

#define GROUP 64
#define MAXT 4096
#define MAXN 4096
#define KMAX 4096

// Scratch (device globals: allocation-free rule)
__device__ uint8_t g_Aq[(size_t)MAXT * KMAX];    // e4m3 quantized activations
__device__ uint8_t g_Bq[(size_t)MAXN * KMAX];    // e4m3 weights
__device__ float   g_Asc[(size_t)MAXT * 64];     // activation scales [T][K/64]
__device__ __half  g_Alr[(size_t)MAXT * 64];     // lr augmented A cols (fp16)
__device__ __half  g_Blr[(size_t)MAXN * 64];     // lr augmented B cols (fp16)
__device__ float   g_LRp[16][MAXT][32];          // lowrank split-K partials
__device__ int     g_wfmt;                       // 0=int8, 1=int32, 2=float32

// ---------------------------------------------------------------------------
// helpers
// ---------------------------------------------------------------------------
__device__ __forceinline__ uint32_t smem_u32(const void* p) {
    uint32_t a;
    asm("{ .reg .u64 t; cvta.to.shared.u64 t, %1; cvt.u32.u64 %0, t; }" : "=r"(a) : "l"(p));
    return a;
}
#define SWZ(o) ((o) ^ ((((uint32_t)(o)) >> 3) & 0x70))

__device__ __forceinline__ void cp16(uint32_t s, const void* g) {
    asm volatile("cp.async.cg.shared.global [%0], [%1], 16;" :: "r"(s), "l"(g));
}
__device__ __forceinline__ void cp8(uint32_t s, const void* g) {
    asm volatile("cp.async.ca.shared.global [%0], [%1], 8;" :: "r"(s), "l"(g));
}
__device__ __forceinline__ void ldmx4(uint32_t& r0, uint32_t& r1, uint32_t& r2, uint32_t& r3,
                                      uint32_t addr) {
    asm volatile("ldmatrix.sync.aligned.m8n8.x4.shared.b16 {%0,%1,%2,%3}, [%4];"
                 : "=r"(r0), "=r"(r1), "=r"(r2), "=r"(r3) : "r"(addr));
}
__device__ __forceinline__ void mma16816(float& c0, float& c1, float& c2, float& c3,
                                         uint32_t a0, uint32_t a1, uint32_t a2, uint32_t a3,
                                         uint32_t b0, uint32_t b1) {
    asm volatile("mma.sync.aligned.m16n8k16.row.col.f32.f16.f16.f32 "
                 "{%0,%1,%2,%3}, {%4,%5,%6,%7}, {%8,%9}, {%0,%1,%2,%3};"
                 : "+f"(c0), "+f"(c1), "+f"(c2), "+f"(c3)
                 : "r"(a0), "r"(a1), "r"(a2), "r"(a3), "r"(b0), "r"(b1));
}
__device__ __forceinline__ void mmafp8(float& c0, float& c1, float& c2, float& c3,
                                       uint32_t a0, uint32_t a1, uint32_t a2, uint32_t a3,
                                       uint32_t b0, uint32_t b1) {
    asm volatile("mma.sync.aligned.m16n8k32.row.col.f32.e4m3.e4m3.f32 "
                 "{%0,%1,%2,%3}, {%4,%5,%6,%7}, {%8,%9}, {%0,%1,%2,%3};"
                 : "+f"(c0), "+f"(c1), "+f"(c2), "+f"(c3)
                 : "r"(a0), "r"(a1), "r"(a2), "r"(a3), "r"(b0), "r"(b1));
}
// pack 4 floats (integral, in [-8,7]) into 4 e4m3 bytes (exact for these values)
__device__ __forceinline__ uint32_t pack_e4m3_4(float f0, float f1, float f2, float f3) {
    uint16_t lo, hi;
    asm("cvt.rn.satfinite.e4m3x2.f32 %0, %1, %2;" : "=h"(lo) : "f"(f1), "f"(f0));
    asm("cvt.rn.satfinite.e4m3x2.f32 %0, %1, %2;" : "=h"(hi) : "f"(f3), "f"(f2));
    return (uint32_t)lo | ((uint32_t)hi << 16);
}

// ---------------------------------------------------------------------------
// Kernel 0: detect storage format of q_w (harness may widen int8)
// ---------------------------------------------------------------------------
__global__ void detect_wfmt_kernel(const void* qw, int total) {
    __shared__ int ok_i32, ok_f32;
    if (threadIdx.x == 0) { ok_i32 = 1; ok_f32 = 1; }
    __syncthreads();
    const int*   wi = (const int*)qw;
    const float* wf = (const float*)qw;
    int n = total < 1024 ? total : 1024;
    int bad_i = 0, bad_f = 0;
    for (int i = threadIdx.x; i < n; i += blockDim.x) {
        int v = wi[i];
        if (v < -8 || v > 7) bad_i = 1;
        float f = wf[i];
        if (!(f == rintf(f) && fabsf(f) <= 8.f)) bad_f = 1;
    }
    if (bad_i) atomicAnd(&ok_i32, 0);
    if (bad_f) atomicAnd(&ok_f32, 0);
    __syncthreads();
    if (threadIdx.x == 0)
        g_wfmt = ok_i32 ? 1 : (ok_f32 ? 2 : 0);
}

// ---------------------------------------------------------------------------
// Fused prep kernel: blockIdx ranges dispatch to
//   [0, LRB)        lowrank split-K partials FUSED with activation quant
//   [LRB, LRB+PB)   weight pack -> e4m3
//   [.., +AB)       B augmented lr columns
// The LR blocks read x exactly once: each (tb, kb) block holds a 128x64
// x*smooth tile in smem per subtile, uses it for the lowrank FMA pass AND
// for per-group int4 quantization (scale bit-identical to reference).
// ---------------------------------------------------------------------------
__global__ void __launch_bounds__(256) prep_kernel(
    const float* __restrict__ x, const float* __restrict__ smooth,
    const float* __restrict__ pd, const float* __restrict__ pu,
    const void* __restrict__ qw,
    int T, int K, int R, int N,
    int LRB, int PB, int AB)
{
    __shared__ float xs[128 * 68];    // 128 tokens x 64 k (stride 68, 16B-mult)
    __shared__ float pdt[64 * 33];    // 64 kk x 32 r
    int tid = threadIdx.x;
    int b = blockIdx.x;

    if (b < LRB) {
        // ---- lowrank split-K partials + fused quant: 16 slices x (T/128) ----
        int kb = b & 15, tb = b >> 4;
        int t0 = tb * 128;
        int k0 = kb * 256;               // 256-wide slice = 4 subtiles of 64
        int tg = tid >> 3, rb = (tid & 7) * 4;
        int trow = tid >> 1, half = tid & 1;   // quant pairing

        float acc[4][4];
#pragma unroll
        for (int i = 0; i < 4; ++i)
#pragma unroll
            for (int j = 0; j < 4; ++j) acc[i][j] = 0.f;

        for (int st = 0; st < 4; ++st) {
            int ks = k0 + st * 64;
            // load x*smooth tile: 128 rows x 16 float4 = 2048 -> 8 per thread
#pragma unroll
            for (int i = 0; i < 8; ++i) {
                int idx4 = tid + i * 256;
                int row = idx4 >> 4, c4 = idx4 & 15;
                float4 v = *reinterpret_cast<const float4*>(
                    x + (size_t)(t0 + row) * K + ks + c4 * 4);
                float4 s = *reinterpret_cast<const float4*>(smooth + ks + c4 * 4);
                v.x *= s.x; v.y *= s.y; v.z *= s.z; v.w *= s.w;
                *reinterpret_cast<float4*>(&xs[row * 68 + c4 * 4]) = v;
            }
            // load pd tile transposed: 64 kk x 32 r = 2048 -> 8 per thread
#pragma unroll
            for (int i = 0; i < 8; ++i) {
                int e = tid + i * 256;
                int kk = e >> 5, r = e & 31;
                pdt[kk * 33 + r] = (r < R) ? pd[(size_t)(ks + kk) * R + r] : 0.f;
            }
            __syncthreads();

            // lowrank FMA pass over 64 kk
#pragma unroll 8
            for (int kk = 0; kk < 64; ++kk) {
                float p0 = pdt[kk * 33 + rb + 0];
                float p1 = pdt[kk * 33 + rb + 1];
                float p2 = pdt[kk * 33 + rb + 2];
                float p3 = pdt[kk * 33 + rb + 3];
#pragma unroll
                for (int i = 0; i < 4; ++i) {
                    float xv = xs[(tg * 4 + i) * 68 + kk];
                    acc[i][0] = fmaf(xv, p0, acc[i][0]);
                    acc[i][1] = fmaf(xv, p1, acc[i][1]);
                    acc[i][2] = fmaf(xv, p2, acc[i][2]);
                    acc[i][3] = fmaf(xv, p3, acc[i][3]);
                }
            }

            // fused quant: 2 threads per (token, group-of-64); each handles 32
            {
                const float* xr = &xs[trow * 68 + half * 32];
                float amax = 0.f;
#pragma unroll
                for (int j = 0; j < 8; ++j) {
                    float4 v = *reinterpret_cast<const float4*>(xr + j * 4);
                    amax = fmaxf(amax, fmaxf(fmaxf(fabsf(v.x), fabsf(v.y)),
                                             fmaxf(fabsf(v.z), fabsf(v.w))));
                }
                float other = __shfl_xor_sync(0xffffffff, amax, 1);
                amax = fmaxf(amax, other);
                float scale = fmaxf(amax * (1.0f / 7.0f), 1e-8f);
                float inv = 1.0f / scale;
                if (half == 0)
                    g_Asc[(size_t)(t0 + trow) * 64 + (ks >> 6)] = scale;

                uint32_t outp[8];
#pragma unroll
                for (int j = 0; j < 8; ++j) {
                    float4 v = *reinterpret_cast<const float4*>(xr + j * 4);
                    float q0 = fminf(fmaxf(rintf(v.x * inv), -8.f), 7.f);
                    float q1 = fminf(fmaxf(rintf(v.y * inv), -8.f), 7.f);
                    float q2 = fminf(fmaxf(rintf(v.z * inv), -8.f), 7.f);
                    float q3 = fminf(fmaxf(rintf(v.w * inv), -8.f), 7.f);
                    outp[j] = pack_e4m3_4(q0, q1, q2, q3);
                }
                uint8_t* dst = g_Aq + (size_t)(t0 + trow) * 4096 + ks + half * 32;
                int4 w0, w1;
                w0.x = outp[0]; w0.y = outp[1]; w0.z = outp[2]; w0.w = outp[3];
                w1.x = outp[4]; w1.y = outp[5]; w1.z = outp[6]; w1.w = outp[7];
                *reinterpret_cast<int4*>(dst) = w0;
                *reinterpret_cast<int4*>(dst + 16) = w1;
            }
            __syncthreads();
        }
#pragma unroll
        for (int i = 0; i < 4; ++i) {
            int t = t0 + tg * 4 + i;
#pragma unroll
            for (int j = 0; j < 4; ++j)
                g_LRp[kb][t][rb + j] = acc[i][j];
        }
        return;
    }
    b -= LRB;

    if (b < PB) {
        // ---- weight pack -> e4m3 (format-adaptive) ----
        int idx = b * 256 + tid;     // one per 16 weights
        int per_row = K / 16;
        if (idx >= N * per_row) return;
        size_t base = (size_t)idx * 16;

        uint32_t out[4];
        int fmt = g_wfmt;
        if (fmt == 1) {
            const int4* p = reinterpret_cast<const int4*>((const int*)qw + base);
#pragma unroll
            for (int i = 0; i < 4; ++i) {
                int4 v = p[i];
                out[i] = pack_e4m3_4((float)v.x, (float)v.y, (float)v.z, (float)v.w);
            }
        } else if (fmt == 2) {
            const float4* p = reinterpret_cast<const float4*>((const float*)qw + base);
#pragma unroll
            for (int i = 0; i < 4; ++i) {
                float4 v = p[i];
                out[i] = pack_e4m3_4(v.x, v.y, v.z, v.w);
            }
        } else {
            const int8_t* p = (const int8_t*)qw + base;
#pragma unroll
            for (int i = 0; i < 4; ++i)
                out[i] = pack_e4m3_4((float)p[i * 4 + 0], (float)p[i * 4 + 1],
                                     (float)p[i * 4 + 2], (float)p[i * 4 + 3]);
        }
        int4 w;
        w.x = out[0]; w.y = out[1]; w.z = out[2]; w.w = out[3];
        *reinterpret_cast<int4*>(g_Bq + base) = w;
        return;
    }
    b -= PB;

    {
        // ---- B augmented lr columns ----
        int n = b * 256 + tid;
        if (n >= N) return;
        __half* dst = g_Blr + (size_t)n * 64;
#pragma unroll 8
        for (int r = 0; r < 64; ++r)
            dst[r] = __float2half((r < R) ? pu[(size_t)r * N + n] : 0.f);
    }
}

// ---------------------------------------------------------------------------
// Reduce lowrank partials -> g_Alr (fp16), zero cols 32..63
// ---------------------------------------------------------------------------
__global__ void lowrank_reduce_kernel(int T) {
    int i = blockIdx.x * 256 + threadIdx.x;
    if (i >= T * 64) return;
    int t = i >> 6, r = i & 63;
    float s = 0.f;
    if (r < 32) {
#pragma unroll
        for (int k = 0; k < 16; ++k) s += g_LRp[k][t][r];
    }
    g_Alr[(size_t)t * 64 + r] = __float2half(s);
}

// ---------------------------------------------------------------------------
// Main GEMM (R11 config — measured best, 562us). TILE_M=64 x TILE_N=128,
// 256 threads (8 warps, 32x32 warp tile), launch_bounds(256,2).
// 32 fp8 chunks (k=128, e4m3 MMA + per-group rescale) + 1 fp16 lr chunk,
// 3-stage cp.async pipeline.
// ---------------------------------------------------------------------------
#define THREADS 256
#define TILE_M 64
#define TILE_N 128
#define NCH 32                 // fp8 chunks (k=4096); chunk NCH = fp16 lr
#define OFF_B   8192           // A tile 64x128B = 8K
#define OFF_ASC 24576          // B tile 128x128B = 16K
#define OFF_WSC 25088          // asc 64 rows x 8B = 512
#define BUFSZ   26112          // + wsc 128 rows x 8B = 1024
#define STAGES 3
#define GEMM_SMEM (STAGES * BUFSZ)   // 78336

__device__ __forceinline__ void load_chunk(uint32_t sb, int buf, int c,
                                           int m0, int n0, const float* ws, int tid) {
    uint32_t base = sb + buf * BUFSZ;
    const char* Asrc;
    const char* Bsrc;
    int stride;
    if (c < NCH) {
        Asrc = reinterpret_cast<const char*>(g_Aq) + (size_t)m0 * 4096 + c * 128;
        Bsrc = reinterpret_cast<const char*>(g_Bq) + (size_t)n0 * 4096 + c * 128;
        stride = 4096;
    } else {
        Asrc = reinterpret_cast<const char*>(g_Alr) + (size_t)m0 * 128;
        Bsrc = reinterpret_cast<const char*>(g_Blr) + (size_t)n0 * 128;
        stride = 128;
    }
    // A: 64 rows x 8 x 16B = 512 pieces
#pragma unroll
    for (int i = 0; i < 2; ++i) {
        int idx = tid + i * 256;
        int row = idx >> 3, pc = idx & 7;
        uint32_t so = SWZ(row * 128 + pc * 16);
        cp16(base + so, Asrc + (size_t)row * stride + pc * 16);
    }
    // B: 128 rows x 8 x 16B = 1024 pieces
#pragma unroll
    for (int i = 0; i < 4; ++i) {
        int idx = tid + i * 256;
        int row = idx >> 3, pc = idx & 7;
        uint32_t so = SWZ(row * 128 + pc * 16);
        cp16(base + OFF_B + so, Bsrc + (size_t)row * stride + pc * 16);
    }
    if (c < NCH) {
        if (tid < 64)
            cp8(base + OFF_ASC + tid * 8, g_Asc + ((size_t)(m0 + tid) * 64 + 2 * c));
        else if (tid < 192)
            cp8(base + OFF_WSC + (tid - 64) * 8, ws + ((size_t)(n0 + tid - 64) * 64 + 2 * c));
    }
}

__global__ void __launch_bounds__(THREADS, 2) gemm_kernel(
    const float* __restrict__ ws, const float* __restrict__ bias,
    float* __restrict__ out, int T, int Nout)
{
    extern __shared__ char smem[];
    uint32_t sb = smem_u32(smem);
    int tid = threadIdx.x, wid = tid >> 5, lid = tid & 31;
    int wm = wid >> 2;               // 0..1  (32 rows)
    int wn = wid & 3;                // 0..3  (32 cols)
    int m0 = blockIdx.y * TILE_M;
    int n0 = blockIdx.x * TILE_N;

    // ldmatrix lane geometry (bytes within 128B rows, SW128)
    int r8 = lid & 7, sel = lid >> 3;
    int aRow[2], aXor[2];
#pragma unroll
    for (int mt = 0; mt < 2; ++mt) {
        int row = wm * 32 + mt * 16 + (sel & 1) * 8 + r8;
        aRow[mt] = row * 128;
        aXor[mt] = (row & 7) << 4;
    }
    int aByte = (sel >> 1) * 16;
    int bRow[2], bXor[2];
#pragma unroll
    for (int pb = 0; pb < 2; ++pb) {
        int row = wn * 32 + pb * 16 + (sel >> 1) * 8 + r8;
        bRow[pb] = row * 128;
        bXor[pb] = (row & 7) << 4;
    }
    int bByte = (sel & 1) * 16;

    // scale lookup indices
    int sr0 = wm * 32 + (lid >> 2);          // + mt*16 ; +8 for second row
    int sc0 = wn * 32 + (lid & 3) * 2;       // + nt*8  ; +1 second col

    float accf[2][4][4];
#pragma unroll
    for (int mt = 0; mt < 2; ++mt)
#pragma unroll
        for (int nt = 0; nt < 4; ++nt)
#pragma unroll
            for (int i = 0; i < 4; ++i) accf[mt][nt][i] = 0.f;

    load_chunk(sb, 0, 0, m0, n0, ws, tid);
    asm volatile("cp.async.commit_group;" ::: "memory");
    load_chunk(sb, 1, 1, m0, n0, ws, tid);
    asm volatile("cp.async.commit_group;" ::: "memory");

    for (int c = 0; c <= NCH; ++c) {
        if (c < NCH) { asm volatile("cp.async.wait_group 1;" ::: "memory"); }
        else         { asm volatile("cp.async.wait_group 0;" ::: "memory"); }
        __syncthreads();
        if (c + 2 <= NCH) {
            load_chunk(sb, (c + 2) % STAGES, c + 2, m0, n0, ws, tid);
            asm volatile("cp.async.commit_group;" ::: "memory");
        }
        int buf = c % STAGES;
        uint32_t ab = sb + buf * BUFSZ;
        uint32_t bb = ab + OFF_B;

        if (c < NCH) {
            const float* asc_s = reinterpret_cast<const float*>(smem + buf * BUFSZ + OFF_ASC);
            const float* wsc_s = reinterpret_cast<const float*>(smem + buf * BUFSZ + OFF_WSC);
#pragma unroll
            for (int grp = 0; grp < 2; ++grp) {
                float dg[2][4][4];
#pragma unroll
                for (int mt = 0; mt < 2; ++mt)
#pragma unroll
                    for (int nt = 0; nt < 4; ++nt)
#pragma unroll
                        for (int i = 0; i < 4; ++i) dg[mt][nt][i] = 0.f;

#pragma unroll
                for (int ks2 = 0; ks2 < 2; ++ks2) {
                    int koff = grp * 64 + ks2 * 32;
                    uint32_t a[2][4];
#pragma unroll
                    for (int mt = 0; mt < 2; ++mt)
                        ldmx4(a[mt][0], a[mt][1], a[mt][2], a[mt][3],
                              ab + aRow[mt] + ((koff + aByte) ^ aXor[mt]));
                    uint32_t b[4][2];
#pragma unroll
                    for (int pb = 0; pb < 2; ++pb) {
                        uint32_t r0, r1, r2, r3;
                        ldmx4(r0, r1, r2, r3,
                              bb + bRow[pb] + ((koff + bByte) ^ bXor[pb]));
                        b[pb * 2 + 0][0] = r0; b[pb * 2 + 0][1] = r1;
                        b[pb * 2 + 1][0] = r2; b[pb * 2 + 1][1] = r3;
                    }
#pragma unroll
                    for (int mt = 0; mt < 2; ++mt)
#pragma unroll
                        for (int nt = 0; nt < 4; ++nt)
                            mmafp8(dg[mt][nt][0], dg[mt][nt][1], dg[mt][nt][2], dg[mt][nt][3],
                                   a[mt][0], a[mt][1], a[mt][2], a[mt][3],
                                   b[nt][0], b[nt][1]);
                }
                // per-group rescale into f32 accumulators (group sums are exact ints)
#pragma unroll
                for (int mt = 0; mt < 2; ++mt) {
                    float a0 = asc_s[(sr0 + mt * 16) * 2 + grp];
                    float a1 = asc_s[(sr0 + mt * 16 + 8) * 2 + grp];
#pragma unroll
                    for (int nt = 0; nt < 4; ++nt) {
                        float w0 = wsc_s[(sc0 + nt * 8) * 2 + grp];
                        float w1 = wsc_s[(sc0 + nt * 8 + 1) * 2 + grp];
                        accf[mt][nt][0] = fmaf(dg[mt][nt][0], a0 * w0, accf[mt][nt][0]);
                        accf[mt][nt][1] = fmaf(dg[mt][nt][1], a0 * w1, accf[mt][nt][1]);
                        accf[mt][nt][2] = fmaf(dg[mt][nt][2], a1 * w0, accf[mt][nt][2]);
                        accf[mt][nt][3] = fmaf(dg[mt][nt][3], a1 * w1, accf[mt][nt][3]);
                    }
                }
            }
        } else {
            // fp16 low-rank chunk (64 halves = 128B rows, same geometry)
#pragma unroll
            for (int ks = 0; ks < 4; ++ks) {
                uint32_t a[2][4];
#pragma unroll
                for (int mt = 0; mt < 2; ++mt)
                    ldmx4(a[mt][0], a[mt][1], a[mt][2], a[mt][3],
                          ab + aRow[mt] + ((ks * 32 + aByte) ^ aXor[mt]));
                uint32_t b[4][2];
#pragma unroll
                for (int pb = 0; pb < 2; ++pb) {
                    uint32_t r0, r1, r2, r3;
                    ldmx4(r0, r1, r2, r3,
                          bb + bRow[pb] + ((ks * 32 + bByte) ^ bXor[pb]));
                    b[pb * 2 + 0][0] = r0; b[pb * 2 + 0][1] = r1;
                    b[pb * 2 + 1][0] = r2; b[pb * 2 + 1][1] = r3;
                }
#pragma unroll
                for (int mt = 0; mt < 2; ++mt)
#pragma unroll
                    for (int nt = 0; nt < 4; ++nt)
                        mma16816(accf[mt][nt][0], accf[mt][nt][1], accf[mt][nt][2], accf[mt][nt][3],
                                 a[mt][0], a[mt][1], a[mt][2], a[mt][3],
                                 b[nt][0], b[nt][1]);
            }
        }
    }

    // epilogue: direct fragment stores + bias
    int g = lid >> 2, tg2 = lid & 3;
#pragma unroll
    for (int nt = 0; nt < 4; ++nt) {
        int col = n0 + wn * 32 + nt * 8 + tg2 * 2;
        float2 bv = *reinterpret_cast<const float2*>(bias + col);
#pragma unroll
        for (int mt = 0; mt < 2; ++mt) {
            int row0 = m0 + wm * 32 + mt * 16 + g;
            float2 v0; v0.x = accf[mt][nt][0] + bv.x; v0.y = accf[mt][nt][1] + bv.y;
            *reinterpret_cast<float2*>(out + (size_t)row0 * Nout + col) = v0;
            float2 v1; v1.x = accf[mt][nt][2] + bv.x; v1.y = accf[mt][nt][3] + bv.y;
            *reinterpret_cast<float2*>(out + (size_t)(row0 + 8) * Nout + col) = v1;
        }
    }
}

// ---------------------------------------------------------------------------
// Host launcher
// ---------------------------------------------------------------------------
extern "C" void kernel_launch(void* const* d_in, const int* in_sizes, int n_in,
                              void* d_out, int out_size) {
    const float*  x      = (const float*)d_in[0];
    const void*   qw     = (const void*)d_in[1];
    const float*  ws     = (const float*)d_in[2];
    const float*  pd     = (const float*)d_in[3];
    const float*  pu     = (const float*)d_in[4];
    const float*  smooth = (const float*)d_in[5];
    const float*  bias   = (const float*)d_in[6];
    float* out = (float*)d_out;

    int K    = in_sizes[5];           // smooth
    int Nout = in_sizes[6];           // bias
    int T    = in_sizes[0] / K;       // x
    int R    = in_sizes[3] / K;       // proj_down

    detect_wfmt_kernel<<<1, 256>>>(qw, in_sizes[1]);

    int LRB = (T / 128) * 16;                       // 512 (quant fused here)
    int PB  = (Nout * (K / 16) + 255) / 256;        // 4096
    int AB  = (Nout + 255) / 256;                   // 16
    prep_kernel<<<LRB + PB + AB, 256>>>(x, smooth, pd, pu, qw,
                                        T, K, R, Nout, LRB, PB, AB);
    lowrank_reduce_kernel<<<(T * 64 + 255) / 256, 256>>>(T);

    cudaFuncSetAttribute(gemm_kernel, cudaFuncAttributeMaxDynamicSharedMemorySize, GEMM_SMEM);
    dim3 grid(Nout / TILE_N, T / TILE_M);
    gemm_kernel<<<grid, THREADS, GEMM_SMEM>>>(ws, bias, out, T, Nout);
}